// round 14
// baseline (speedup 1.0000x reference)
#include <cuda_runtime.h>
#include <cuda_bf16.h>
#include <cuda_fp16.h>
#include <cstdint>

#define BB 2
#define SS_ 2048
#define DD 1024
#define HH 16
#define HD 64
#define M_TOT (BB * SS_)        // 4096
#define BH (BB * HH)            // 32
#define SSQ ((size_t)SS_ * SS_) // 4194304 per (b,h)

#define LDSB 72                 // 16-bit elems per smem row (144B, 16B multiple)
#define G_STAGE_BYTES (4 * 128 * LDSB * 2)     // 73728
#define G_PIPE_SMEM   (2 * G_STAGE_BYTES)      // 147456
#define F_Q_BYTES     (2 * 64 * LDSB * 2)      // 18432
#define F_STAGE_BYTES (4 * 64 * LDSB * 2)      // 36864
#define F_SMEM        (F_Q_BYTES + 2 * F_STAGE_BYTES)  // 92160

// -------- scratch (~380 MB, proven range) --------
__device__ __align__(256) __nv_bfloat16 g_xh[(size_t)M_TOT * DD];
__device__ __align__(256) __nv_bfloat16 g_xl[(size_t)M_TOT * DD];
__device__ __align__(256) __nv_bfloat16 g_wth[(size_t)4 * DD * DD];   // W^T hi (q,k,v,o)
__device__ __align__(256) __nv_bfloat16 g_wtl[(size_t)4 * DD * DD];
__device__ __align__(256) __nv_bfloat16 g_qh[(size_t)BH * SS_ * HD];  // pre-scaled by 1/8
__device__ __align__(256) __nv_bfloat16 g_ql[(size_t)BH * SS_ * HD];
__device__ __align__(256) __nv_bfloat16 g_kh[(size_t)BH * SS_ * HD];
__device__ __align__(256) __nv_bfloat16 g_kl[(size_t)BH * SS_ * HD];
__device__ __align__(256) __half       g_vth[(size_t)BH * HD * SS_];  // V^T fp16 hi [bh,dh,s]
__device__ __align__(256) __half       g_vtl[(size_t)BH * HD * SS_];  // V^T fp16 lo
__device__ __align__(256) __nv_bfloat16 g_ch[(size_t)M_TOT * DD];     // ctx [b,s,h*64+dh]
__device__ __align__(256) __nv_bfloat16 g_cl[(size_t)M_TOT * DD];
__device__ __align__(256) float g_sm[(size_t)BH * SS_];               // final row max
__device__ __align__(256) float g_sl[(size_t)BH * SS_];               // final row sum
__device__ __align__(256) __half g_p16[(size_t)BH * SSQ];             // exp(s - nm_kt)
__device__ __align__(256) float g_tm[(size_t)BH * 32 * SS_];          // nm per (bh, kt, q)

// ======================= small helpers ======================================
__device__ __forceinline__ void split2(float v, __nv_bfloat16& hi, __nv_bfloat16& lo) {
    hi = __float2bfloat16(v);
    lo = __float2bfloat16(v - __bfloat162float(hi));
}

__device__ __forceinline__ void split2h(float v, __half& hi, __half& lo) {
    hi = __float2half_rn(v);
    lo = __float2half_rn(v - __half2float(hi));
}

__device__ __forceinline__ uint32_t smem_u32(const void* p) {
    uint32_t a;
    asm("{ .reg .u64 t; cvta.to.shared.u64 t, %1; cvt.u32.u64 %0, t; }" : "=r"(a) : "l"(p));
    return a;
}

__device__ __forceinline__ void ldsm4(uint32_t* r, uint32_t addr) {
    asm volatile("ldmatrix.sync.aligned.m8n8.x4.shared.b16 {%0,%1,%2,%3}, [%4];"
                 : "=r"(r[0]), "=r"(r[1]), "=r"(r[2]), "=r"(r[3]) : "r"(addr));
}

__device__ __forceinline__ void mma16816(float* d, const uint32_t* a, const uint32_t* b) {
    asm volatile(
        "mma.sync.aligned.m16n8k16.row.col.f32.bf16.bf16.f32 "
        "{%0,%1,%2,%3}, {%4,%5,%6,%7}, {%8,%9}, {%0,%1,%2,%3};"
        : "+f"(d[0]), "+f"(d[1]), "+f"(d[2]), "+f"(d[3])
        : "r"(a[0]), "r"(a[1]), "r"(a[2]), "r"(a[3]), "r"(b[0]), "r"(b[1]));
}

__device__ __forceinline__ void mma16816f(float* d, const uint32_t* a, const uint32_t* b) {
    asm volatile(
        "mma.sync.aligned.m16n8k16.row.col.f32.f16.f16.f32 "
        "{%0,%1,%2,%3}, {%4,%5,%6,%7}, {%8,%9}, {%0,%1,%2,%3};"
        : "+f"(d[0]), "+f"(d[1]), "+f"(d[2]), "+f"(d[3])
        : "r"(a[0]), "r"(a[1]), "r"(a[2]), "r"(a[3]), "r"(b[0]), "r"(b[1]));
}

__device__ __forceinline__ void cp_async16(uint32_t saddr, const void* gptr) {
    asm volatile("cp.async.cg.shared.global [%0], [%1], 16;" :: "r"(saddr), "l"(gptr));
}
__device__ __forceinline__ void cp_async_commit() {
    asm volatile("cp.async.commit_group;" ::: "memory");
}
__device__ __forceinline__ void cp_async_wait0() {
    asm volatile("cp.async.wait_group 0;" ::: "memory");
}

// ======================= prep kernels =======================================
__global__ __launch_bounds__(256) void split_x_kernel(const float* __restrict__ x)
{
    size_t i = (size_t)blockIdx.x * 256 + threadIdx.x;
    if (i < (size_t)M_TOT * DD) {
        __nv_bfloat16 h, l;
        split2(x[i], h, l);
        g_xh[i] = h; g_xl[i] = l;
    }
}

// fused: all 4 weights transposed+split in one launch (which = blockIdx.z)
__global__ __launch_bounds__(256) void transpose_split_w_kernel(
    const float* __restrict__ W0, const float* __restrict__ W1,
    const float* __restrict__ W2, const float* __restrict__ W3)
{
    __shared__ __align__(16) float t[32][33];
    const int tx = threadIdx.x, ty = threadIdx.y;   // (32,8)
    const int n0 = blockIdx.x * 32, k0 = blockIdx.y * 32;
    const int which = blockIdx.z;
    const float* __restrict__ W =
        (which == 0) ? W0 : (which == 1) ? W1 : (which == 2) ? W2 : W3;
    __nv_bfloat16* __restrict__ th = g_wth + (size_t)which * DD * DD;
    __nv_bfloat16* __restrict__ tl = g_wtl + (size_t)which * DD * DD;

#pragma unroll
    for (int j = 0; j < 4; j++)
        t[ty + 8 * j][tx] = W[(size_t)(k0 + ty + 8 * j) * DD + n0 + tx];
    __syncthreads();
#pragma unroll
    for (int j = 0; j < 4; j++) {
        float v = t[tx][ty + 8 * j];
        __nv_bfloat16 hi, lo; split2(v, hi, lo);
        size_t di = (size_t)(n0 + ty + 8 * j) * DD + k0 + tx;
        th[di] = hi; tl[di] = lo;
    }
}

// ============================================================================
// 128x128-tile split-bf16 mma GEMM, BK=64, 2-stage cp.async (validated).
// mode_sel: -1 -> mode = blockIdx.z (0 q / 1 k / 2 v fused launch) ; 3 -> out.
// mode 2 now writes V^T as fp16 hi/lo.
// ============================================================================
__global__ __launch_bounds__(256) void gemm_mma_kernel(
    int mode_sel, const float* __restrict__ bias0, const float* __restrict__ bias1,
    const float* __restrict__ bias2, float* __restrict__ fout)
{
    extern __shared__ __align__(16) __nv_bfloat16 dynsm[];

    const int mode = (mode_sel < 0) ? (int)blockIdx.z : mode_sel;
    const float* __restrict__ bias =
        (mode == 1) ? bias1 : (mode == 2) ? bias2 : bias0;

    const __nv_bfloat16* Ah = (mode == 3) ? g_ch : g_xh;
    const __nv_bfloat16* Al = (mode == 3) ? g_cl : g_xl;
    const __nv_bfloat16* Bh = g_wth + (size_t)mode * DD * DD;
    const __nv_bfloat16* Bl = g_wtl + (size_t)mode * DD * DD;
    const int K = DD;

    const int m0 = blockIdx.x * 128;
    const int n0 = blockIdx.y * 128;
    const int tid = threadIdx.x;
    const int wid = tid >> 5;
    const int lane = tid & 31;
    const uint32_t sbase = smem_u32(dynsm);

    const int wy = wid >> 1;
    const int wx = wid & 1;
    const int a_r = lane & 15;
    const int a_c = (lane >> 4) << 3;
    const int b_r = ((lane >> 4) << 3) | (lane & 7);
    const int b_c = ((lane >> 3) & 1) << 3;

    float acc[2][8][4] = {};

    const int niter = K >> 6;

    auto fill = [&](int it, int stage) {
        const int k0 = it << 6;
        const uint32_t stb = sbase + stage * G_STAGE_BYTES;
        for (int idx = tid; idx < 4096; idx += 256) {
            int c = idx & 7;
            int r = (idx >> 3) & 127;
            int sel = idx >> 10;
            const __nv_bfloat16* src;
            if (sel == 0)      src = Ah + (size_t)(m0 + r) * K + k0;
            else if (sel == 1) src = Al + (size_t)(m0 + r) * K + k0;
            else if (sel == 2) src = Bh + (size_t)(n0 + r) * K + k0;
            else               src = Bl + (size_t)(n0 + r) * K + k0;
            uint32_t daddr = stb + (uint32_t)(sel * 128 * LDSB + r * LDSB + c * 8) * 2u;
            cp_async16(daddr, src + c * 8);
        }
    };

    fill(0, 0);
    cp_async_commit();
    int stage = 0;

    for (int it = 0; it < niter; ++it) {
        cp_async_wait0();
        __syncthreads();
        if (it + 1 < niter) { fill(it + 1, stage ^ 1); cp_async_commit(); }

        const uint32_t stb = sbase + stage * G_STAGE_BYTES;
        const uint32_t sAh = stb;
        const uint32_t sAl = stb + (uint32_t)(128 * LDSB) * 2u;
        const uint32_t sBh = stb + (uint32_t)(2 * 128 * LDSB) * 2u;
        const uint32_t sBl = stb + (uint32_t)(3 * 128 * LDSB) * 2u;

#pragma unroll
        for (int ks = 0; ks < 4; ks++) {
            uint32_t afh[2][4], afl[2][4];
#pragma unroll
            for (int i = 0; i < 2; i++) {
                uint32_t off = (uint32_t)((wy * 32 + i * 16 + a_r) * LDSB + ks * 16 + a_c) * 2u;
                ldsm4(afh[i], sAh + off);
                ldsm4(afl[i], sAl + off);
            }
            uint32_t bfh[4][4], bfl[4][4];
#pragma unroll
            for (int jn = 0; jn < 4; jn++) {
                uint32_t off = (uint32_t)((wx * 64 + jn * 16 + b_r) * LDSB + ks * 16 + b_c) * 2u;
                ldsm4(bfh[jn], sBh + off);
                ldsm4(bfl[jn], sBl + off);
            }
#pragma unroll
            for (int i = 0; i < 2; i++)
#pragma unroll
                for (int jn = 0; jn < 4; jn++)
#pragma unroll
                    for (int hf = 0; hf < 2; hf++) {
                        int j8 = jn * 2 + hf;
                        mma16816(acc[i][j8], afh[i], &bfh[jn][hf * 2]);
                        mma16816(acc[i][j8], afh[i], &bfl[jn][hf * 2]);
                        mma16816(acc[i][j8], afl[i], &bfh[jn][hf * 2]);
                    }
        }
        __syncthreads();
        stage ^= 1;
    }

    const int er = lane >> 2;
    const int ec = (lane & 3) * 2;
#pragma unroll
    for (int i = 0; i < 2; i++) {
#pragma unroll
        for (int j8 = 0; j8 < 8; j8++) {
#pragma unroll
            for (int half = 0; half < 2; half++) {
                int m = m0 + wy * 32 + i * 16 + er + half * 8;
                int n = n0 + wx * 64 + j8 * 8 + ec;
                float v0 = acc[i][j8][half * 2 + 0];
                float v1 = acc[i][j8][half * 2 + 1];
                if (mode == 3) {
                    float2 o = make_float2(v0 + bias[n], v1 + bias[n + 1]);
                    *(float2*)(fout + (size_t)m * DD + n) = o;
                } else {
                    int b = m >> 11, s = m & (SS_ - 1);
                    int h = n >> 6, dh = n & 63;
                    float b0 = v0 + bias[n], b1 = v1 + bias[n + 1];
                    if (mode == 0) { b0 *= 0.125f; b1 *= 0.125f; }
                    if (mode == 2) {       // V^T fp16 hi/lo [bh,dh,s]
                        __half h0, l0, h1, l1;
                        split2h(b0, h0, l0);
                        split2h(b1, h1, l1);
                        size_t di = (((size_t)(b * HH + h)) * HD + dh) * SS_ + s;
                        g_vth[di] = h0; g_vtl[di] = l0;
                        g_vth[di + SS_] = h1; g_vtl[di + SS_] = l1;
                    } else {
                        __nv_bfloat16 h0, l0, h1, l1;
                        split2(b0, h0, l0);
                        split2(b1, h1, l1);
                        size_t di = (((size_t)(b * HH + h)) * SS_ + s) * HD + dh;
                        if (mode == 0) {
                            *(__nv_bfloat162*)(g_qh + di) = __halves2bfloat162(h0, h1);
                            *(__nv_bfloat162*)(g_ql + di) = __halves2bfloat162(l0, l1);
                        } else {
                            *(__nv_bfloat162*)(g_kh + di) = __halves2bfloat162(h0, h1);
                            *(__nv_bfloat162*)(g_kl + di) = __halves2bfloat162(l0, l1);
                        }
                    }
                }
            }
        }
    }
}

// ============================================================================
// FLASH attention: per (bh, 64 q-rows), 128 threads, 2 CTAs/SM.
// Scores: 3-term bf16 (validated). PV: fp16 P16 @ fp16 V hi/lo (2 mmas).
// P16 fragments double as the mean-pass spill values.
// ============================================================================
__global__ __launch_bounds__(128, 2) void flash_kernel()
{
    extern __shared__ __align__(16) __nv_bfloat16 dynsm[];

    const int bh = blockIdx.y;
    const int m0 = blockIdx.x * 64;
    const int tid = threadIdx.x;
    const int wid = tid >> 5;          // 0..3
    const int lane = tid & 31;

    const __nv_bfloat16* Qh = g_qh + (size_t)bh * SS_ * HD;
    const __nv_bfloat16* Ql = g_ql + (size_t)bh * SS_ * HD;
    const __nv_bfloat16* Kh = g_kh + (size_t)bh * SS_ * HD;
    const __nv_bfloat16* Kl = g_kl + (size_t)bh * SS_ * HD;
    const __half* Vh = g_vth + (size_t)bh * HD * SS_;
    const __half* Vl = g_vtl + (size_t)bh * HD * SS_;

    const uint32_t sbase = smem_u32(dynsm);
    const uint32_t sQh = sbase;
    const uint32_t sQl = sbase + (uint32_t)(64 * LDSB) * 2u;
    const uint32_t stages = sbase + F_Q_BYTES;

    const int a_r = lane & 15;
    const int a_c = (lane >> 4) << 3;
    const int b_r = ((lane >> 4) << 3) | (lane & 7);
    const int b_c = ((lane >> 3) & 1) << 3;
    const int er = lane >> 2;
    const int ec = (lane & 3) * 2;

    // ---- load Q tile ----
    for (int idx = tid; idx < 1024; idx += 128) {
        int c = idx & 7;
        int r = (idx >> 3) & 63;
        int sel = idx >> 9;
        const __nv_bfloat16* src = (sel ? Ql : Qh) + (size_t)(m0 + r) * HD;
        uint32_t dst = (sel ? sQl : sQh) + (uint32_t)(r * LDSB + c * 8) * 2u;
        uint4 val = ((const uint4*)src)[c];
        *(uint4*)(dynsm + (dst - sbase) / 2) = val;
    }

    auto fill = [&](int kt, int stage) {
        const int k0 = kt * 64;
        const uint32_t stb = stages + stage * F_STAGE_BYTES;
        for (int idx = tid; idx < 2048; idx += 128) {
            int c = idx & 7;
            int r = (idx >> 3) & 63;
            int sel = idx >> 9;
            const void* src;
            if (sel == 0)      src = Kh + (size_t)(k0 + r) * HD + c * 8;
            else if (sel == 1) src = Kl + (size_t)(k0 + r) * HD + c * 8;
            else if (sel == 2) src = Vh + (size_t)r * SS_ + k0 + c * 8;
            else               src = Vl + (size_t)r * SS_ + k0 + c * 8;
            uint32_t daddr = stb + (uint32_t)(sel * 64 * LDSB + r * LDSB + c * 8) * 2u;
            cp_async16(daddr, src);
        }
    };

    fill(0, 0);
    cp_async_commit();
    __syncthreads();

    uint32_t qfh[4][4], qfl[4][4];
#pragma unroll
    for (int ks = 0; ks < 4; ks++) {
        uint32_t off = (uint32_t)((wid * 16 + a_r) * LDSB + ks * 16 + a_c) * 2u;
        ldsm4(qfh[ks], sQh + off);
        ldsm4(qfl[ks], sQl + off);
    }

    float o[8][4] = {};
    float mr0 = -1e30f, mr1 = -1e30f, lr0 = 0.f, lr1 = 0.f;
    int stage = 0;

    for (int kt = 0; kt < 32; ++kt) {
        cp_async_wait0();
        __syncthreads();
        if (kt + 1 < 32) { fill(kt + 1, stage ^ 1); cp_async_commit(); }

        const uint32_t stb = stages + stage * F_STAGE_BYTES;
        const uint32_t sKh = stb;
        const uint32_t sKl = stb + (uint32_t)(64 * LDSB) * 2u;
        const uint32_t sVh = stb + (uint32_t)(2 * 64 * LDSB) * 2u;
        const uint32_t sVl = stb + (uint32_t)(3 * 64 * LDSB) * 2u;

        // ---- scores: 3-term bf16 ----
        float s[8][4] = {};
#pragma unroll
        for (int ks = 0; ks < 4; ks++) {
            uint32_t bfh[4][4], bfl[4][4];
#pragma unroll
            for (int jn = 0; jn < 4; jn++) {
                uint32_t off = (uint32_t)((jn * 16 + b_r) * LDSB + ks * 16 + b_c) * 2u;
                ldsm4(bfh[jn], sKh + off);
                ldsm4(bfl[jn], sKl + off);
            }
#pragma unroll
            for (int jn = 0; jn < 4; jn++)
#pragma unroll
                for (int hf = 0; hf < 2; hf++) {
                    int j8 = jn * 2 + hf;
                    mma16816(s[j8], qfh[ks], &bfh[jn][hf * 2]);
                    mma16816(s[j8], qfh[ks], &bfl[jn][hf * 2]);
                    mma16816(s[j8], qfl[ks], &bfh[jn][hf * 2]);
                }
        }

        // ---- online softmax ----
        float mx0 = -1e30f, mx1 = -1e30f;
#pragma unroll
        for (int j8 = 0; j8 < 8; j8++) {
            mx0 = fmaxf(mx0, fmaxf(s[j8][0], s[j8][1]));
            mx1 = fmaxf(mx1, fmaxf(s[j8][2], s[j8][3]));
        }
        mx0 = fmaxf(mx0, __shfl_xor_sync(~0u, mx0, 1));
        mx0 = fmaxf(mx0, __shfl_xor_sync(~0u, mx0, 2));
        mx1 = fmaxf(mx1, __shfl_xor_sync(~0u, mx1, 1));
        mx1 = fmaxf(mx1, __shfl_xor_sync(~0u, mx1, 2));

        float nm0 = fmaxf(mr0, mx0), nm1 = fmaxf(mr1, mx1);
        float c0 = __expf(mr0 - nm0), c1 = __expf(mr1 - nm1);

        float sum0 = 0.f, sum1 = 0.f;
#pragma unroll
        for (int j8 = 0; j8 < 8; j8++) {
            s[j8][0] = __expf(s[j8][0] - nm0); sum0 += s[j8][0];
            s[j8][1] = __expf(s[j8][1] - nm0); sum0 += s[j8][1];
            s[j8][2] = __expf(s[j8][2] - nm1); sum1 += s[j8][2];
            s[j8][3] = __expf(s[j8][3] - nm1); sum1 += s[j8][3];
        }
        sum0 += __shfl_xor_sync(~0u, sum0, 1);
        sum0 += __shfl_xor_sync(~0u, sum0, 2);
        sum1 += __shfl_xor_sync(~0u, sum1, 1);
        sum1 += __shfl_xor_sync(~0u, sum1, 2);

        lr0 = lr0 * c0 + sum0;
        lr1 = lr1 * c1 + sum1;
        mr0 = nm0; mr1 = nm1;

#pragma unroll
        for (int j8 = 0; j8 < 8; j8++) {
            o[j8][0] *= c0; o[j8][1] *= c0;
            o[j8][2] *= c1; o[j8][3] *= c1;
        }

        // ---- convert P to fp16 fragments (also the spill values) ----
        uint32_t pf[4][4];
#pragma unroll
        for (int u = 0; u < 4; u++) {
            const float* pa = s[2 * u];
            const float* pb = s[2 * u + 1];
            __half2 t;
            t = __floats2half2_rn(pa[0], pa[1]); pf[u][0] = *(uint32_t*)&t;
            t = __floats2half2_rn(pa[2], pa[3]); pf[u][1] = *(uint32_t*)&t;
            t = __floats2half2_rn(pb[0], pb[1]); pf[u][2] = *(uint32_t*)&t;
            t = __floats2half2_rn(pb[2], pb[3]); pf[u][3] = *(uint32_t*)&t;
        }

        // ---- spill P16 + tile max ----
        {
            const int q0 = m0 + wid * 16 + er;
            uint32_t* P0 = (uint32_t*)(g_p16 + (size_t)bh * SSQ + (size_t)q0 * SS_ + kt * 64 + ec);
            uint32_t* P1 = (uint32_t*)(g_p16 + (size_t)bh * SSQ + (size_t)(q0 + 8) * SS_ + kt * 64 + ec);
#pragma unroll
            for (int u = 0; u < 4; u++) {
                P0[(2 * u) * 4]     = pf[u][0];
                P0[(2 * u + 1) * 4] = pf[u][2];
                P1[(2 * u) * 4]     = pf[u][1];
                P1[(2 * u + 1) * 4] = pf[u][3];
            }
            if ((lane & 3) == 0) {
                size_t ti = ((size_t)bh * 32 + kt) * SS_ + q0;
                g_tm[ti] = nm0;
                g_tm[ti + 8] = nm1;
            }
        }

        // ---- PV: o += P16 @ (Vh16 + Vl16)  (2 fp16 mmas) ----
#pragma unroll
        for (int u = 0; u < 4; u++) {
#pragma unroll
            for (int jn = 0; jn < 4; jn++) {
                uint32_t off = (uint32_t)((jn * 16 + b_r) * LDSB + u * 16 + b_c) * 2u;
                uint32_t vfh[4], vfl[4];
                ldsm4(vfh, sVh + off);
                ldsm4(vfl, sVl + off);
#pragma unroll
                for (int hf = 0; hf < 2; hf++) {
                    int j8 = jn * 2 + hf;
                    mma16816f(o[j8], pf[u], &vfh[hf * 2]);
                    mma16816f(o[j8], pf[u], &vfl[hf * 2]);
                }
            }
        }
        stage ^= 1;
    }

    // ---- epilogue: normalize, write ctx + stats ----
    const float inv0 = 1.0f / lr0, inv1 = 1.0f / lr1;
    const int b = bh >> 4, h = bh & 15;
#pragma unroll
    for (int j8 = 0; j8 < 8; j8++) {
#pragma unroll
        for (int half = 0; half < 2; half++) {
            int m = m0 + wid * 16 + er + half * 8;
            int n = j8 * 8 + ec;
            float inv = half ? inv1 : inv0;
            float v0 = o[j8][half * 2 + 0] * inv;
            float v1 = o[j8][half * 2 + 1] * inv;
            __nv_bfloat16 h0, l0, h1, l1;
            split2(v0, h0, l0);
            split2(v1, h1, l1);
            size_t di = ((size_t)(b * SS_ + m)) * DD + h * HD + n;
            *(__nv_bfloat162*)(g_ch + di) = __halves2bfloat162(h0, h1);
            *(__nv_bfloat162*)(g_cl + di) = __halves2bfloat162(l0, l1);
        }
    }
    if ((lane & 3) == 0) {
        size_t r0 = (size_t)bh * SS_ + m0 + wid * 16 + er;
        g_sm[r0] = mr0;      g_sl[r0] = lr0;
        g_sm[r0 + 8] = mr1;  g_sl[r0 + 8] = lr1;
    }
}

// ============================================================================
// mean kernel: pure streaming pass over P16 (validated R13).
// ============================================================================
__global__ __launch_bounds__(256) void mean_kernel(float* __restrict__ attn_mean)
{
    const int bq = blockIdx.x;           // 0..B*S-1
    const int b = bq >> 11;
    const int q = bq & (SS_ - 1);
    const int tid = threadIdx.x;
    const int col0 = tid * 8;
    const int kt = tid >> 3;

    float acc[8] = {};

    for (int h = 0; h < HH; h++) {
        const int bh = b * HH + h;
        const size_t srow = (size_t)bh * SS_ + q;
        float f = __expf(g_tm[((size_t)bh * 32 + kt) * SS_ + q] - g_sm[srow]) / g_sl[srow];

        uint4 pv = *(const uint4*)(g_p16 + (size_t)bh * SSQ + (size_t)q * SS_ + col0);
        const __half2* ph = (const __half2*)&pv;
#pragma unroll
        for (int j = 0; j < 4; j++) {
            float2 v = __half22float2(ph[j]);
            acc[2 * j]     += v.x * f;
            acc[2 * j + 1] += v.y * f;
        }
    }

    const float inv16 = 1.0f / 16.0f;
    float* dst = attn_mean + (size_t)bq * SS_ + col0;
    float4 o0 = make_float4(acc[0] * inv16, acc[1] * inv16, acc[2] * inv16, acc[3] * inv16);
    float4 o1 = make_float4(acc[4] * inv16, acc[5] * inv16, acc[6] * inv16, acc[7] * inv16);
    *(float4*)(dst) = o0;
    *(float4*)(dst + 4) = o1;
}

// ============================================================================
extern "C" void kernel_launch(void* const* d_in, const int* in_sizes, int n_in,
                              void* d_out, int out_size)
{
    const float* x  = (const float*)d_in[0];
    const float* Wq = (const float*)d_in[1];
    const float* bq = (const float*)d_in[2];
    const float* Wk = (const float*)d_in[3];
    const float* bk = (const float*)d_in[4];
    const float* Wv = (const float*)d_in[5];
    const float* bv = (const float*)d_in[6];
    const float* Wo = (const float*)d_in[7];
    const float* bo = (const float*)d_in[8];

    float* out = (float*)d_out;                        // [B,S,D]
    float* attn_mean = out + (size_t)BB * SS_ * DD;    // [B,S,S]

    cudaFuncSetAttribute(gemm_mma_kernel, cudaFuncAttributeMaxDynamicSharedMemorySize, G_PIPE_SMEM);
    cudaFuncSetAttribute(flash_kernel,    cudaFuncAttributeMaxDynamicSharedMemorySize, F_SMEM);

    // prep
    split_x_kernel<<<(M_TOT * DD + 255) / 256, 256>>>(x);
    dim3 tw(32, 8), gw(DD / 32, DD / 32, 4);
    transpose_split_w_kernel<<<gw, tw>>>(Wq, Wk, Wv, Wo);

    // q/k/v projections fused (mode = blockIdx.z)
    dim3 gqkv(M_TOT / 128, DD / 128, 3); // (32,8,3)
    gemm_mma_kernel<<<gqkv, 256, G_PIPE_SMEM>>>(-1, bq, bk, bv, nullptr);

    // flash attention: ctx + stats + P16 spill
    dim3 gf(SS_ / 64, BH);               // (32,32)
    flash_kernel<<<gf, 128, F_SMEM>>>();

    // attn_mean: streaming pass
    mean_kernel<<<BB * SS_, 256>>>(attn_mean);

    // out projection
    dim3 gp(M_TOT / 128, DD / 128);      // (32,8)
    gemm_mma_kernel<<<gp, 256, G_PIPE_SMEM>>>(3, bo, nullptr, nullptr, out);
}

// round 15
// speedup vs baseline: 1.0810x; 1.0810x over previous
#include <cuda_runtime.h>
#include <cuda_bf16.h>
#include <cuda_fp16.h>
#include <cstdint>

#define BB 2
#define SS_ 2048
#define DD 1024
#define HH 16
#define HD 64
#define M_TOT (BB * SS_)        // 4096
#define BH (BB * HH)            // 32
#define SSQ ((size_t)SS_ * SS_) // 4194304 per (b,h)

#define LDSB 72                 // 16-bit elems per smem row (144B, 16B multiple)
#define G_STAGE_BYTES (4 * 128 * LDSB * 2)     // 73728
#define G_PIPE_SMEM   (2 * G_STAGE_BYTES)      // 147456
#define F_Q_BYTES     (2 * 64 * LDSB * 2)      // 18432
#define F_STAGE_BYTES (4 * 64 * LDSB * 2)      // 36864
#define F_SMEM        (F_Q_BYTES + F_STAGE_BYTES)      // 55296 (single stage, 4 CTA/SM)

// -------- scratch (~380 MB, proven range) --------
__device__ __align__(256) __nv_bfloat16 g_xh[(size_t)M_TOT * DD];
__device__ __align__(256) __nv_bfloat16 g_xl[(size_t)M_TOT * DD];
__device__ __align__(256) __nv_bfloat16 g_wth[(size_t)4 * DD * DD];   // W^T hi (q,k,v,o)
__device__ __align__(256) __nv_bfloat16 g_wtl[(size_t)4 * DD * DD];
__device__ __align__(256) __nv_bfloat16 g_qh[(size_t)BH * SS_ * HD];  // pre-scaled by 1/8
__device__ __align__(256) __nv_bfloat16 g_ql[(size_t)BH * SS_ * HD];
__device__ __align__(256) __nv_bfloat16 g_kh[(size_t)BH * SS_ * HD];
__device__ __align__(256) __nv_bfloat16 g_kl[(size_t)BH * SS_ * HD];
__device__ __align__(256) __half       g_vth[(size_t)BH * HD * SS_];  // V^T fp16 hi [bh,dh,s]
__device__ __align__(256) __half       g_vtl[(size_t)BH * HD * SS_];  // V^T fp16 lo
__device__ __align__(256) __nv_bfloat16 g_ch[(size_t)M_TOT * DD];     // ctx [b,s,h*64+dh]
__device__ __align__(256) __nv_bfloat16 g_cl[(size_t)M_TOT * DD];
__device__ __align__(256) float g_sm[(size_t)BH * SS_];               // final row max
__device__ __align__(256) float g_sl[(size_t)BH * SS_];               // final row sum
__device__ __align__(256) __half g_p16[(size_t)BH * SSQ];             // exp(s - nm_kt)
__device__ __align__(256) float g_tm[(size_t)BH * 32 * SS_];          // nm per (bh, kt, q)

// ======================= small helpers ======================================
__device__ __forceinline__ void split2(float v, __nv_bfloat16& hi, __nv_bfloat16& lo) {
    hi = __float2bfloat16(v);
    lo = __float2bfloat16(v - __bfloat162float(hi));
}

__device__ __forceinline__ void split2h(float v, __half& hi, __half& lo) {
    hi = __float2half_rn(v);
    lo = __float2half_rn(v - __half2float(hi));
}

__device__ __forceinline__ uint32_t smem_u32(const void* p) {
    uint32_t a;
    asm("{ .reg .u64 t; cvta.to.shared.u64 t, %1; cvt.u32.u64 %0, t; }" : "=r"(a) : "l"(p));
    return a;
}

__device__ __forceinline__ void ldsm4(uint32_t* r, uint32_t addr) {
    asm volatile("ldmatrix.sync.aligned.m8n8.x4.shared.b16 {%0,%1,%2,%3}, [%4];"
                 : "=r"(r[0]), "=r"(r[1]), "=r"(r[2]), "=r"(r[3]) : "r"(addr));
}

__device__ __forceinline__ void mma16816(float* d, const uint32_t* a, const uint32_t* b) {
    asm volatile(
        "mma.sync.aligned.m16n8k16.row.col.f32.bf16.bf16.f32 "
        "{%0,%1,%2,%3}, {%4,%5,%6,%7}, {%8,%9}, {%0,%1,%2,%3};"
        : "+f"(d[0]), "+f"(d[1]), "+f"(d[2]), "+f"(d[3])
        : "r"(a[0]), "r"(a[1]), "r"(a[2]), "r"(a[3]), "r"(b[0]), "r"(b[1]));
}

__device__ __forceinline__ void mma16816f(float* d, const uint32_t* a, const uint32_t* b) {
    asm volatile(
        "mma.sync.aligned.m16n8k16.row.col.f32.f16.f16.f32 "
        "{%0,%1,%2,%3}, {%4,%5,%6,%7}, {%8,%9}, {%0,%1,%2,%3};"
        : "+f"(d[0]), "+f"(d[1]), "+f"(d[2]), "+f"(d[3])
        : "r"(a[0]), "r"(a[1]), "r"(a[2]), "r"(a[3]), "r"(b[0]), "r"(b[1]));
}

__device__ __forceinline__ void cp_async16(uint32_t saddr, const void* gptr) {
    asm volatile("cp.async.cg.shared.global [%0], [%1], 16;" :: "r"(saddr), "l"(gptr));
}
__device__ __forceinline__ void cp_async_commit() {
    asm volatile("cp.async.commit_group;" ::: "memory");
}
__device__ __forceinline__ void cp_async_wait0() {
    asm volatile("cp.async.wait_group 0;" ::: "memory");
}

// ======================= prep kernels =======================================
__global__ __launch_bounds__(256) void split_x_kernel(const float* __restrict__ x)
{
    size_t i = (size_t)blockIdx.x * 256 + threadIdx.x;
    if (i < (size_t)M_TOT * DD) {
        __nv_bfloat16 h, l;
        split2(x[i], h, l);
        g_xh[i] = h; g_xl[i] = l;
    }
}

// fused: all 4 weights transposed+split in one launch (which = blockIdx.z)
__global__ __launch_bounds__(256) void transpose_split_w_kernel(
    const float* __restrict__ W0, const float* __restrict__ W1,
    const float* __restrict__ W2, const float* __restrict__ W3)
{
    __shared__ __align__(16) float t[32][33];
    const int tx = threadIdx.x, ty = threadIdx.y;   // (32,8)
    const int n0 = blockIdx.x * 32, k0 = blockIdx.y * 32;
    const int which = blockIdx.z;
    const float* __restrict__ W =
        (which == 0) ? W0 : (which == 1) ? W1 : (which == 2) ? W2 : W3;
    __nv_bfloat16* __restrict__ th = g_wth + (size_t)which * DD * DD;
    __nv_bfloat16* __restrict__ tl = g_wtl + (size_t)which * DD * DD;

#pragma unroll
    for (int j = 0; j < 4; j++)
        t[ty + 8 * j][tx] = W[(size_t)(k0 + ty + 8 * j) * DD + n0 + tx];
    __syncthreads();
#pragma unroll
    for (int j = 0; j < 4; j++) {
        float v = t[tx][ty + 8 * j];
        __nv_bfloat16 hi, lo; split2(v, hi, lo);
        size_t di = (size_t)(n0 + ty + 8 * j) * DD + k0 + tx;
        th[di] = hi; tl[di] = lo;
    }
}

// ============================================================================
// 128x128-tile split-bf16 mma GEMM, BK=64, 2-stage cp.async (validated).
// mode_sel: -1 -> mode = blockIdx.z (0 q / 1 k / 2 v fused launch) ; 3 -> out.
// ============================================================================
__global__ __launch_bounds__(256) void gemm_mma_kernel(
    int mode_sel, const float* __restrict__ bias0, const float* __restrict__ bias1,
    const float* __restrict__ bias2, float* __restrict__ fout)
{
    extern __shared__ __align__(16) __nv_bfloat16 dynsm[];

    const int mode = (mode_sel < 0) ? (int)blockIdx.z : mode_sel;
    const float* __restrict__ bias =
        (mode == 1) ? bias1 : (mode == 2) ? bias2 : bias0;

    const __nv_bfloat16* Ah = (mode == 3) ? g_ch : g_xh;
    const __nv_bfloat16* Al = (mode == 3) ? g_cl : g_xl;
    const __nv_bfloat16* Bh = g_wth + (size_t)mode * DD * DD;
    const __nv_bfloat16* Bl = g_wtl + (size_t)mode * DD * DD;
    const int K = DD;

    const int m0 = blockIdx.x * 128;
    const int n0 = blockIdx.y * 128;
    const int tid = threadIdx.x;
    const int wid = tid >> 5;
    const int lane = tid & 31;
    const uint32_t sbase = smem_u32(dynsm);

    const int wy = wid >> 1;
    const int wx = wid & 1;
    const int a_r = lane & 15;
    const int a_c = (lane >> 4) << 3;
    const int b_r = ((lane >> 4) << 3) | (lane & 7);
    const int b_c = ((lane >> 3) & 1) << 3;

    float acc[2][8][4] = {};

    const int niter = K >> 6;

    auto fill = [&](int it, int stage) {
        const int k0 = it << 6;
        const uint32_t stb = sbase + stage * G_STAGE_BYTES;
        for (int idx = tid; idx < 4096; idx += 256) {
            int c = idx & 7;
            int r = (idx >> 3) & 127;
            int sel = idx >> 10;
            const __nv_bfloat16* src;
            if (sel == 0)      src = Ah + (size_t)(m0 + r) * K + k0;
            else if (sel == 1) src = Al + (size_t)(m0 + r) * K + k0;
            else if (sel == 2) src = Bh + (size_t)(n0 + r) * K + k0;
            else               src = Bl + (size_t)(n0 + r) * K + k0;
            uint32_t daddr = stb + (uint32_t)(sel * 128 * LDSB + r * LDSB + c * 8) * 2u;
            cp_async16(daddr, src + c * 8);
        }
    };

    fill(0, 0);
    cp_async_commit();
    int stage = 0;

    for (int it = 0; it < niter; ++it) {
        cp_async_wait0();
        __syncthreads();
        if (it + 1 < niter) { fill(it + 1, stage ^ 1); cp_async_commit(); }

        const uint32_t stb = sbase + stage * G_STAGE_BYTES;
        const uint32_t sAh = stb;
        const uint32_t sAl = stb + (uint32_t)(128 * LDSB) * 2u;
        const uint32_t sBh = stb + (uint32_t)(2 * 128 * LDSB) * 2u;
        const uint32_t sBl = stb + (uint32_t)(3 * 128 * LDSB) * 2u;

#pragma unroll
        for (int ks = 0; ks < 4; ks++) {
            uint32_t afh[2][4], afl[2][4];
#pragma unroll
            for (int i = 0; i < 2; i++) {
                uint32_t off = (uint32_t)((wy * 32 + i * 16 + a_r) * LDSB + ks * 16 + a_c) * 2u;
                ldsm4(afh[i], sAh + off);
                ldsm4(afl[i], sAl + off);
            }
            uint32_t bfh[4][4], bfl[4][4];
#pragma unroll
            for (int jn = 0; jn < 4; jn++) {
                uint32_t off = (uint32_t)((wx * 64 + jn * 16 + b_r) * LDSB + ks * 16 + b_c) * 2u;
                ldsm4(bfh[jn], sBh + off);
                ldsm4(bfl[jn], sBl + off);
            }
#pragma unroll
            for (int i = 0; i < 2; i++)
#pragma unroll
                for (int jn = 0; jn < 4; jn++)
#pragma unroll
                    for (int hf = 0; hf < 2; hf++) {
                        int j8 = jn * 2 + hf;
                        mma16816(acc[i][j8], afh[i], &bfh[jn][hf * 2]);
                        mma16816(acc[i][j8], afh[i], &bfl[jn][hf * 2]);
                        mma16816(acc[i][j8], afl[i], &bfh[jn][hf * 2]);
                    }
        }
        __syncthreads();
        stage ^= 1;
    }

    const int er = lane >> 2;
    const int ec = (lane & 3) * 2;
#pragma unroll
    for (int i = 0; i < 2; i++) {
#pragma unroll
        for (int j8 = 0; j8 < 8; j8++) {
#pragma unroll
            for (int half = 0; half < 2; half++) {
                int m = m0 + wy * 32 + i * 16 + er + half * 8;
                int n = n0 + wx * 64 + j8 * 8 + ec;
                float v0 = acc[i][j8][half * 2 + 0];
                float v1 = acc[i][j8][half * 2 + 1];
                if (mode == 3) {
                    float2 o = make_float2(v0 + bias[n], v1 + bias[n + 1]);
                    *(float2*)(fout + (size_t)m * DD + n) = o;
                } else {
                    int b = m >> 11, s = m & (SS_ - 1);
                    int h = n >> 6, dh = n & 63;
                    float b0 = v0 + bias[n], b1 = v1 + bias[n + 1];
                    if (mode == 0) { b0 *= 0.125f; b1 *= 0.125f; }
                    if (mode == 2) {       // V^T fp16 hi/lo [bh,dh,s]
                        __half h0, l0, h1, l1;
                        split2h(b0, h0, l0);
                        split2h(b1, h1, l1);
                        size_t di = (((size_t)(b * HH + h)) * HD + dh) * SS_ + s;
                        g_vth[di] = h0; g_vtl[di] = l0;
                        g_vth[di + SS_] = h1; g_vtl[di + SS_] = l1;
                    } else {
                        __nv_bfloat16 h0, l0, h1, l1;
                        split2(b0, h0, l0);
                        split2(b1, h1, l1);
                        size_t di = (((size_t)(b * HH + h)) * SS_ + s) * HD + dh;
                        if (mode == 0) {
                            *(__nv_bfloat162*)(g_qh + di) = __halves2bfloat162(h0, h1);
                            *(__nv_bfloat162*)(g_ql + di) = __halves2bfloat162(l0, l1);
                        } else {
                            *(__nv_bfloat162*)(g_kh + di) = __halves2bfloat162(h0, h1);
                            *(__nv_bfloat162*)(g_kl + di) = __halves2bfloat162(l0, l1);
                        }
                    }
                }
            }
        }
    }
}

// ============================================================================
// FLASH attention: per (bh, 64 q-rows), 128 threads, SINGLE K/V stage,
// 4 CTAs/SM (inter-CTA latency hiding). Scores: 3-term bf16. PV: 2 fp16 mmas.
// ============================================================================
__global__ __launch_bounds__(128, 4) void flash_kernel()
{
    extern __shared__ __align__(16) __nv_bfloat16 dynsm[];

    const int bh = blockIdx.y;
    const int m0 = blockIdx.x * 64;
    const int tid = threadIdx.x;
    const int wid = tid >> 5;          // 0..3
    const int lane = tid & 31;

    const __nv_bfloat16* Qh = g_qh + (size_t)bh * SS_ * HD;
    const __nv_bfloat16* Ql = g_ql + (size_t)bh * SS_ * HD;
    const __nv_bfloat16* Kh = g_kh + (size_t)bh * SS_ * HD;
    const __nv_bfloat16* Kl = g_kl + (size_t)bh * SS_ * HD;
    const __half* Vh = g_vth + (size_t)bh * HD * SS_;
    const __half* Vl = g_vtl + (size_t)bh * HD * SS_;

    const uint32_t sbase = smem_u32(dynsm);
    const uint32_t sQh = sbase;
    const uint32_t sQl = sbase + (uint32_t)(64 * LDSB) * 2u;
    const uint32_t stb = sbase + F_Q_BYTES;      // single K/V stage
    const uint32_t sKh = stb;
    const uint32_t sKl = stb + (uint32_t)(64 * LDSB) * 2u;
    const uint32_t sVh = stb + (uint32_t)(2 * 64 * LDSB) * 2u;
    const uint32_t sVl = stb + (uint32_t)(3 * 64 * LDSB) * 2u;

    const int a_r = lane & 15;
    const int a_c = (lane >> 4) << 3;
    const int b_r = ((lane >> 4) << 3) | (lane & 7);
    const int b_c = ((lane >> 3) & 1) << 3;
    const int er = lane >> 2;
    const int ec = (lane & 3) * 2;

    // ---- load Q tile ----
    for (int idx = tid; idx < 1024; idx += 128) {
        int c = idx & 7;
        int r = (idx >> 3) & 63;
        int sel = idx >> 9;
        const __nv_bfloat16* src = (sel ? Ql : Qh) + (size_t)(m0 + r) * HD;
        uint32_t dst = (sel ? sQl : sQh) + (uint32_t)(r * LDSB + c * 8) * 2u;
        uint4 val = ((const uint4*)src)[c];
        *(uint4*)(dynsm + (dst - sbase) / 2) = val;
    }

    auto fill = [&](int kt) {
        const int k0 = kt * 64;
        for (int idx = tid; idx < 2048; idx += 128) {
            int c = idx & 7;
            int r = (idx >> 3) & 63;
            int sel = idx >> 9;
            const void* src;
            if (sel == 0)      src = Kh + (size_t)(k0 + r) * HD + c * 8;
            else if (sel == 1) src = Kl + (size_t)(k0 + r) * HD + c * 8;
            else if (sel == 2) src = Vh + (size_t)r * SS_ + k0 + c * 8;
            else               src = Vl + (size_t)r * SS_ + k0 + c * 8;
            uint32_t daddr = stb + (uint32_t)(sel * 64 * LDSB + r * LDSB + c * 8) * 2u;
            cp_async16(daddr, src);
        }
    };

    __syncthreads();   // Q tile visible

    uint32_t qfh[4][4], qfl[4][4];
#pragma unroll
    for (int ks = 0; ks < 4; ks++) {
        uint32_t off = (uint32_t)((wid * 16 + a_r) * LDSB + ks * 16 + a_c) * 2u;
        ldsm4(qfh[ks], sQh + off);
        ldsm4(qfl[ks], sQl + off);
    }

    float o[8][4] = {};
    float mr0 = -1e30f, mr1 = -1e30f, lr0 = 0.f, lr1 = 0.f;

    for (int kt = 0; kt < 32; ++kt) {
        fill(kt);
        cp_async_commit();
        cp_async_wait0();
        __syncthreads();

        // ---- scores: 3-term bf16 ----
        float s[8][4] = {};
#pragma unroll
        for (int ks = 0; ks < 4; ks++) {
            uint32_t bfh[4][4], bfl[4][4];
#pragma unroll
            for (int jn = 0; jn < 4; jn++) {
                uint32_t off = (uint32_t)((jn * 16 + b_r) * LDSB + ks * 16 + b_c) * 2u;
                ldsm4(bfh[jn], sKh + off);
                ldsm4(bfl[jn], sKl + off);
            }
#pragma unroll
            for (int jn = 0; jn < 4; jn++)
#pragma unroll
                for (int hf = 0; hf < 2; hf++) {
                    int j8 = jn * 2 + hf;
                    mma16816(s[j8], qfh[ks], &bfh[jn][hf * 2]);
                    mma16816(s[j8], qfh[ks], &bfl[jn][hf * 2]);
                    mma16816(s[j8], qfl[ks], &bfh[jn][hf * 2]);
                }
        }

        // ---- online softmax ----
        float mx0 = -1e30f, mx1 = -1e30f;
#pragma unroll
        for (int j8 = 0; j8 < 8; j8++) {
            mx0 = fmaxf(mx0, fmaxf(s[j8][0], s[j8][1]));
            mx1 = fmaxf(mx1, fmaxf(s[j8][2], s[j8][3]));
        }
        mx0 = fmaxf(mx0, __shfl_xor_sync(~0u, mx0, 1));
        mx0 = fmaxf(mx0, __shfl_xor_sync(~0u, mx0, 2));
        mx1 = fmaxf(mx1, __shfl_xor_sync(~0u, mx1, 1));
        mx1 = fmaxf(mx1, __shfl_xor_sync(~0u, mx1, 2));

        float nm0 = fmaxf(mr0, mx0), nm1 = fmaxf(mr1, mx1);
        float c0 = __expf(mr0 - nm0), c1 = __expf(mr1 - nm1);

        float sum0 = 0.f, sum1 = 0.f;
#pragma unroll
        for (int j8 = 0; j8 < 8; j8++) {
            s[j8][0] = __expf(s[j8][0] - nm0); sum0 += s[j8][0];
            s[j8][1] = __expf(s[j8][1] - nm0); sum0 += s[j8][1];
            s[j8][2] = __expf(s[j8][2] - nm1); sum1 += s[j8][2];
            s[j8][3] = __expf(s[j8][3] - nm1); sum1 += s[j8][3];
        }
        sum0 += __shfl_xor_sync(~0u, sum0, 1);
        sum0 += __shfl_xor_sync(~0u, sum0, 2);
        sum1 += __shfl_xor_sync(~0u, sum1, 1);
        sum1 += __shfl_xor_sync(~0u, sum1, 2);

        lr0 = lr0 * c0 + sum0;
        lr1 = lr1 * c1 + sum1;
        mr0 = nm0; mr1 = nm1;

#pragma unroll
        for (int j8 = 0; j8 < 8; j8++) {
            o[j8][0] *= c0; o[j8][1] *= c0;
            o[j8][2] *= c1; o[j8][3] *= c1;
        }

        // ---- P -> fp16 fragments (also spill values) ----
        uint32_t pf[4][4];
#pragma unroll
        for (int u = 0; u < 4; u++) {
            const float* pa = s[2 * u];
            const float* pb = s[2 * u + 1];
            __half2 t;
            t = __floats2half2_rn(pa[0], pa[1]); pf[u][0] = *(uint32_t*)&t;
            t = __floats2half2_rn(pa[2], pa[3]); pf[u][1] = *(uint32_t*)&t;
            t = __floats2half2_rn(pb[0], pb[1]); pf[u][2] = *(uint32_t*)&t;
            t = __floats2half2_rn(pb[2], pb[3]); pf[u][3] = *(uint32_t*)&t;
        }

        // ---- spill P16 + tile max ----
        {
            const int q0 = m0 + wid * 16 + er;
            uint32_t* P0 = (uint32_t*)(g_p16 + (size_t)bh * SSQ + (size_t)q0 * SS_ + kt * 64 + ec);
            uint32_t* P1 = (uint32_t*)(g_p16 + (size_t)bh * SSQ + (size_t)(q0 + 8) * SS_ + kt * 64 + ec);
#pragma unroll
            for (int u = 0; u < 4; u++) {
                P0[(2 * u) * 4]     = pf[u][0];
                P0[(2 * u + 1) * 4] = pf[u][2];
                P1[(2 * u) * 4]     = pf[u][1];
                P1[(2 * u + 1) * 4] = pf[u][3];
            }
            if ((lane & 3) == 0) {
                size_t ti = ((size_t)bh * 32 + kt) * SS_ + q0;
                g_tm[ti] = nm0;
                g_tm[ti + 8] = nm1;
            }
        }

        // ---- PV: o += P16 @ (Vh16 + Vl16) ----
#pragma unroll
        for (int u = 0; u < 4; u++) {
#pragma unroll
            for (int jn = 0; jn < 4; jn++) {
                uint32_t off = (uint32_t)((jn * 16 + b_r) * LDSB + u * 16 + b_c) * 2u;
                uint32_t vfh[4], vfl[4];
                ldsm4(vfh, sVh + off);
                ldsm4(vfl, sVl + off);
#pragma unroll
                for (int hf = 0; hf < 2; hf++) {
                    int j8 = jn * 2 + hf;
                    mma16816f(o[j8], pf[u], &vfh[hf * 2]);
                    mma16816f(o[j8], pf[u], &vfl[hf * 2]);
                }
            }
        }
        __syncthreads();   // all warps done reading stage before next fill
    }

    // ---- epilogue: normalize, write ctx + stats ----
    const float inv0 = 1.0f / lr0, inv1 = 1.0f / lr1;
    const int b = bh >> 4, h = bh & 15;
#pragma unroll
    for (int j8 = 0; j8 < 8; j8++) {
#pragma unroll
        for (int half = 0; half < 2; half++) {
            int m = m0 + wid * 16 + er + half * 8;
            int n = j8 * 8 + ec;
            float inv = half ? inv1 : inv0;
            float v0 = o[j8][half * 2 + 0] * inv;
            float v1 = o[j8][half * 2 + 1] * inv;
            __nv_bfloat16 h0, l0, h1, l1;
            split2(v0, h0, l0);
            split2(v1, h1, l1);
            size_t di = ((size_t)(b * SS_ + m)) * DD + h * HD + n;
            *(__nv_bfloat162*)(g_ch + di) = __halves2bfloat162(h0, h1);
            *(__nv_bfloat162*)(g_cl + di) = __halves2bfloat162(l0, l1);
        }
    }
    if ((lane & 3) == 0) {
        size_t r0 = (size_t)bh * SS_ + m0 + wid * 16 + er;
        g_sm[r0] = mr0;      g_sl[r0] = lr0;
        g_sm[r0 + 8] = mr1;  g_sl[r0 + 8] = lr1;
    }
}

// ============================================================================
// mean kernel: pure streaming pass over P16 (validated R13).
// ============================================================================
__global__ __launch_bounds__(256) void mean_kernel(float* __restrict__ attn_mean)
{
    const int bq = blockIdx.x;           // 0..B*S-1
    const int b = bq >> 11;
    const int q = bq & (SS_ - 1);
    const int tid = threadIdx.x;
    const int col0 = tid * 8;
    const int kt = tid >> 3;

    float acc[8] = {};

    for (int h = 0; h < HH; h++) {
        const int bh = b * HH + h;
        const size_t srow = (size_t)bh * SS_ + q;
        float f = __expf(g_tm[((size_t)bh * 32 + kt) * SS_ + q] - g_sm[srow]) / g_sl[srow];

        uint4 pv = *(const uint4*)(g_p16 + (size_t)bh * SSQ + (size_t)q * SS_ + col0);
        const __half2* ph = (const __half2*)&pv;
#pragma unroll
        for (int j = 0; j < 4; j++) {
            float2 v = __half22float2(ph[j]);
            acc[2 * j]     += v.x * f;
            acc[2 * j + 1] += v.y * f;
        }
    }

    const float inv16 = 1.0f / 16.0f;
    float* dst = attn_mean + (size_t)bq * SS_ + col0;
    float4 o0 = make_float4(acc[0] * inv16, acc[1] * inv16, acc[2] * inv16, acc[3] * inv16);
    float4 o1 = make_float4(acc[4] * inv16, acc[5] * inv16, acc[6] * inv16, acc[7] * inv16);
    *(float4*)(dst) = o0;
    *(float4*)(dst + 4) = o1;
}

// ============================================================================
extern "C" void kernel_launch(void* const* d_in, const int* in_sizes, int n_in,
                              void* d_out, int out_size)
{
    const float* x  = (const float*)d_in[0];
    const float* Wq = (const float*)d_in[1];
    const float* bq = (const float*)d_in[2];
    const float* Wk = (const float*)d_in[3];
    const float* bk = (const float*)d_in[4];
    const float* Wv = (const float*)d_in[5];
    const float* bv = (const float*)d_in[6];
    const float* Wo = (const float*)d_in[7];
    const float* bo = (const float*)d_in[8];

    float* out = (float*)d_out;                        // [B,S,D]
    float* attn_mean = out + (size_t)BB * SS_ * DD;    // [B,S,S]

    cudaFuncSetAttribute(gemm_mma_kernel, cudaFuncAttributeMaxDynamicSharedMemorySize, G_PIPE_SMEM);
    cudaFuncSetAttribute(flash_kernel,    cudaFuncAttributeMaxDynamicSharedMemorySize, F_SMEM);

    // prep
    split_x_kernel<<<(M_TOT * DD + 255) / 256, 256>>>(x);
    dim3 tw(32, 8), gw(DD / 32, DD / 32, 4);
    transpose_split_w_kernel<<<gw, tw>>>(Wq, Wk, Wv, Wo);

    // q/k/v projections fused (mode = blockIdx.z)
    dim3 gqkv(M_TOT / 128, DD / 128, 3); // (32,8,3)
    gemm_mma_kernel<<<gqkv, 256, G_PIPE_SMEM>>>(-1, bq, bk, bv, nullptr);

    // flash attention: ctx + stats + P16 spill (4 CTAs/SM)
    dim3 gf(SS_ / 64, BH);               // (32,32)
    flash_kernel<<<gf, 128, F_SMEM>>>();

    // attn_mean: streaming pass
    mean_kernel<<<BB * SS_, 256>>>(attn_mean);

    // out projection
    dim3 gp(M_TOT / 128, DD / 128);      // (32,8)
    gemm_mma_kernel<<<gp, 256, G_PIPE_SMEM>>>(3, bo, nullptr, nullptr, out);
}

// round 16
// speedup vs baseline: 1.1799x; 1.0915x over previous
#include <cuda_runtime.h>
#include <cuda_bf16.h>
#include <cuda_fp16.h>
#include <cstdint>

#define BB 2
#define SS_ 2048
#define DD 1024
#define HH 16
#define HD 64
#define M_TOT (BB * SS_)        // 4096
#define BH (BB * HH)            // 32
#define SSQ ((size_t)SS_ * SS_) // 4194304 per (b,h)

#define LDSB 72                 // 16-bit elems per smem row (144B, 16B multiple)
#define G_STAGE_BYTES (4 * 128 * LDSB * 2)     // 73728
#define G_PIPE_SMEM   (2 * G_STAGE_BYTES)      // 147456
#define F_Q_BYTES     (2 * 64 * LDSB * 2)      // 18432
#define F_STAGE_BYTES (3 * 64 * LDSB * 2)      // 27648 (Kh, Kl, Vh)
#define F_SMEM        (F_Q_BYTES + F_STAGE_BYTES)      // 46080 (4 CTA/SM)

// -------- scratch (~370 MB, proven range) --------
__device__ __align__(256) __nv_bfloat16 g_xh[(size_t)M_TOT * DD];
__device__ __align__(256) __nv_bfloat16 g_xl[(size_t)M_TOT * DD];
__device__ __align__(256) __nv_bfloat16 g_wth[(size_t)4 * DD * DD];   // W^T hi (q,k,v,o)
__device__ __align__(256) __nv_bfloat16 g_wtl[(size_t)4 * DD * DD];
__device__ __align__(256) __nv_bfloat16 g_qh[(size_t)BH * SS_ * HD];  // pre-scaled by 1/8
__device__ __align__(256) __nv_bfloat16 g_ql[(size_t)BH * SS_ * HD];
__device__ __align__(256) __nv_bfloat16 g_kh[(size_t)BH * SS_ * HD];
__device__ __align__(256) __nv_bfloat16 g_kl[(size_t)BH * SS_ * HD];
__device__ __align__(256) __half       g_vth[(size_t)BH * HD * SS_];  // V^T fp16 [bh,dh,s]
__device__ __align__(256) __nv_bfloat16 g_ch[(size_t)M_TOT * DD];     // ctx [b,s,h*64+dh]
__device__ __align__(256) __nv_bfloat16 g_cl[(size_t)M_TOT * DD];
__device__ __align__(256) float g_sm[(size_t)BH * SS_];               // final row max
__device__ __align__(256) float g_sl[(size_t)BH * SS_];               // final row sum
__device__ __align__(256) __half g_p16[(size_t)BH * SSQ];             // exp(s - nm_kt)
__device__ __align__(256) float g_tm[(size_t)BH * 32 * SS_];          // nm per (bh, kt, q)

// ======================= small helpers ======================================
__device__ __forceinline__ void split2(float v, __nv_bfloat16& hi, __nv_bfloat16& lo) {
    hi = __float2bfloat16(v);
    lo = __float2bfloat16(v - __bfloat162float(hi));
}

__device__ __forceinline__ uint32_t smem_u32(const void* p) {
    uint32_t a;
    asm("{ .reg .u64 t; cvta.to.shared.u64 t, %1; cvt.u32.u64 %0, t; }" : "=r"(a) : "l"(p));
    return a;
}

__device__ __forceinline__ void ldsm4(uint32_t* r, uint32_t addr) {
    asm volatile("ldmatrix.sync.aligned.m8n8.x4.shared.b16 {%0,%1,%2,%3}, [%4];"
                 : "=r"(r[0]), "=r"(r[1]), "=r"(r[2]), "=r"(r[3]) : "r"(addr));
}

__device__ __forceinline__ void mma16816(float* d, const uint32_t* a, const uint32_t* b) {
    asm volatile(
        "mma.sync.aligned.m16n8k16.row.col.f32.bf16.bf16.f32 "
        "{%0,%1,%2,%3}, {%4,%5,%6,%7}, {%8,%9}, {%0,%1,%2,%3};"
        : "+f"(d[0]), "+f"(d[1]), "+f"(d[2]), "+f"(d[3])
        : "r"(a[0]), "r"(a[1]), "r"(a[2]), "r"(a[3]), "r"(b[0]), "r"(b[1]));
}

__device__ __forceinline__ void mma16816f(float* d, const uint32_t* a, const uint32_t* b) {
    asm volatile(
        "mma.sync.aligned.m16n8k16.row.col.f32.f16.f16.f32 "
        "{%0,%1,%2,%3}, {%4,%5,%6,%7}, {%8,%9}, {%0,%1,%2,%3};"
        : "+f"(d[0]), "+f"(d[1]), "+f"(d[2]), "+f"(d[3])
        : "r"(a[0]), "r"(a[1]), "r"(a[2]), "r"(a[3]), "r"(b[0]), "r"(b[1]));
}

__device__ __forceinline__ void cp_async16(uint32_t saddr, const void* gptr) {
    asm volatile("cp.async.cg.shared.global [%0], [%1], 16;" :: "r"(saddr), "l"(gptr));
}
__device__ __forceinline__ void cp_async_commit() {
    asm volatile("cp.async.commit_group;" ::: "memory");
}
__device__ __forceinline__ void cp_async_wait0() {
    asm volatile("cp.async.wait_group 0;" ::: "memory");
}

// ======================= prep kernels =======================================
__global__ __launch_bounds__(256) void split_x_kernel(const float* __restrict__ x)
{
    size_t i = (size_t)blockIdx.x * 256 + threadIdx.x;
    if (i < (size_t)M_TOT * DD) {
        __nv_bfloat16 h, l;
        split2(x[i], h, l);
        g_xh[i] = h; g_xl[i] = l;
    }
}

__global__ __launch_bounds__(256) void transpose_split_w_kernel(
    const float* __restrict__ W0, const float* __restrict__ W1,
    const float* __restrict__ W2, const float* __restrict__ W3)
{
    __shared__ __align__(16) float t[32][33];
    const int tx = threadIdx.x, ty = threadIdx.y;   // (32,8)
    const int n0 = blockIdx.x * 32, k0 = blockIdx.y * 32;
    const int which = blockIdx.z;
    const float* __restrict__ W =
        (which == 0) ? W0 : (which == 1) ? W1 : (which == 2) ? W2 : W3;
    __nv_bfloat16* __restrict__ th = g_wth + (size_t)which * DD * DD;
    __nv_bfloat16* __restrict__ tl = g_wtl + (size_t)which * DD * DD;

#pragma unroll
    for (int j = 0; j < 4; j++)
        t[ty + 8 * j][tx] = W[(size_t)(k0 + ty + 8 * j) * DD + n0 + tx];
    __syncthreads();
#pragma unroll
    for (int j = 0; j < 4; j++) {
        float v = t[tx][ty + 8 * j];
        __nv_bfloat16 hi, lo; split2(v, hi, lo);
        size_t di = (size_t)(n0 + ty + 8 * j) * DD + k0 + tx;
        th[di] = hi; tl[di] = lo;
    }
}

// ============================================================================
// 128x128-tile split-bf16 mma GEMM, BK=64, 2-stage cp.async (validated).
// mode_sel: -1 -> mode = blockIdx.z (0 q / 1 k / 2 v fused launch) ; 3 -> out.
// mode 2 writes V^T as single fp16.
// ============================================================================
__global__ __launch_bounds__(256) void gemm_mma_kernel(
    int mode_sel, const float* __restrict__ bias0, const float* __restrict__ bias1,
    const float* __restrict__ bias2, float* __restrict__ fout)
{
    extern __shared__ __align__(16) __nv_bfloat16 dynsm[];

    const int mode = (mode_sel < 0) ? (int)blockIdx.z : mode_sel;
    const float* __restrict__ bias =
        (mode == 1) ? bias1 : (mode == 2) ? bias2 : bias0;

    const __nv_bfloat16* Ah = (mode == 3) ? g_ch : g_xh;
    const __nv_bfloat16* Al = (mode == 3) ? g_cl : g_xl;
    const __nv_bfloat16* Bh = g_wth + (size_t)mode * DD * DD;
    const __nv_bfloat16* Bl = g_wtl + (size_t)mode * DD * DD;
    const int K = DD;

    const int m0 = blockIdx.x * 128;
    const int n0 = blockIdx.y * 128;
    const int tid = threadIdx.x;
    const int wid = tid >> 5;
    const int lane = tid & 31;
    const uint32_t sbase = smem_u32(dynsm);

    const int wy = wid >> 1;
    const int wx = wid & 1;
    const int a_r = lane & 15;
    const int a_c = (lane >> 4) << 3;
    const int b_r = ((lane >> 4) << 3) | (lane & 7);
    const int b_c = ((lane >> 3) & 1) << 3;

    float acc[2][8][4] = {};

    const int niter = K >> 6;

    auto fill = [&](int it, int stage) {
        const int k0 = it << 6;
        const uint32_t stb = sbase + stage * G_STAGE_BYTES;
        for (int idx = tid; idx < 4096; idx += 256) {
            int c = idx & 7;
            int r = (idx >> 3) & 127;
            int sel = idx >> 10;
            const __nv_bfloat16* src;
            if (sel == 0)      src = Ah + (size_t)(m0 + r) * K + k0;
            else if (sel == 1) src = Al + (size_t)(m0 + r) * K + k0;
            else if (sel == 2) src = Bh + (size_t)(n0 + r) * K + k0;
            else               src = Bl + (size_t)(n0 + r) * K + k0;
            uint32_t daddr = stb + (uint32_t)(sel * 128 * LDSB + r * LDSB + c * 8) * 2u;
            cp_async16(daddr, src + c * 8);
        }
    };

    fill(0, 0);
    cp_async_commit();
    int stage = 0;

    for (int it = 0; it < niter; ++it) {
        cp_async_wait0();
        __syncthreads();
        if (it + 1 < niter) { fill(it + 1, stage ^ 1); cp_async_commit(); }

        const uint32_t stb = sbase + stage * G_STAGE_BYTES;
        const uint32_t sAh = stb;
        const uint32_t sAl = stb + (uint32_t)(128 * LDSB) * 2u;
        const uint32_t sBh = stb + (uint32_t)(2 * 128 * LDSB) * 2u;
        const uint32_t sBl = stb + (uint32_t)(3 * 128 * LDSB) * 2u;

#pragma unroll
        for (int ks = 0; ks < 4; ks++) {
            uint32_t afh[2][4], afl[2][4];
#pragma unroll
            for (int i = 0; i < 2; i++) {
                uint32_t off = (uint32_t)((wy * 32 + i * 16 + a_r) * LDSB + ks * 16 + a_c) * 2u;
                ldsm4(afh[i], sAh + off);
                ldsm4(afl[i], sAl + off);
            }
            uint32_t bfh[4][4], bfl[4][4];
#pragma unroll
            for (int jn = 0; jn < 4; jn++) {
                uint32_t off = (uint32_t)((wx * 64 + jn * 16 + b_r) * LDSB + ks * 16 + b_c) * 2u;
                ldsm4(bfh[jn], sBh + off);
                ldsm4(bfl[jn], sBl + off);
            }
#pragma unroll
            for (int i = 0; i < 2; i++)
#pragma unroll
                for (int jn = 0; jn < 4; jn++)
#pragma unroll
                    for (int hf = 0; hf < 2; hf++) {
                        int j8 = jn * 2 + hf;
                        mma16816(acc[i][j8], afh[i], &bfh[jn][hf * 2]);
                        mma16816(acc[i][j8], afh[i], &bfl[jn][hf * 2]);
                        mma16816(acc[i][j8], afl[i], &bfh[jn][hf * 2]);
                    }
        }
        __syncthreads();
        stage ^= 1;
    }

    const int er = lane >> 2;
    const int ec = (lane & 3) * 2;
#pragma unroll
    for (int i = 0; i < 2; i++) {
#pragma unroll
        for (int j8 = 0; j8 < 8; j8++) {
#pragma unroll
            for (int half = 0; half < 2; half++) {
                int m = m0 + wy * 32 + i * 16 + er + half * 8;
                int n = n0 + wx * 64 + j8 * 8 + ec;
                float v0 = acc[i][j8][half * 2 + 0];
                float v1 = acc[i][j8][half * 2 + 1];
                if (mode == 3) {
                    float2 o = make_float2(v0 + bias[n], v1 + bias[n + 1]);
                    *(float2*)(fout + (size_t)m * DD + n) = o;
                } else {
                    int b = m >> 11, s = m & (SS_ - 1);
                    int h = n >> 6, dh = n & 63;
                    float b0 = v0 + bias[n], b1 = v1 + bias[n + 1];
                    if (mode == 0) { b0 *= 0.125f; b1 *= 0.125f; }
                    if (mode == 2) {       // V^T single fp16 [bh,dh,s]
                        size_t di = (((size_t)(b * HH + h)) * HD + dh) * SS_ + s;
                        g_vth[di] = __float2half_rn(b0);
                        g_vth[di + SS_] = __float2half_rn(b1);
                    } else {
                        __nv_bfloat16 h0, l0, h1, l1;
                        split2(b0, h0, l0);
                        split2(b1, h1, l1);
                        size_t di = (((size_t)(b * HH + h)) * SS_ + s) * HD + dh;
                        if (mode == 0) {
                            *(__nv_bfloat162*)(g_qh + di) = __halves2bfloat162(h0, h1);
                            *(__nv_bfloat162*)(g_ql + di) = __halves2bfloat162(l0, l1);
                        } else {
                            *(__nv_bfloat162*)(g_kh + di) = __halves2bfloat162(h0, h1);
                            *(__nv_bfloat162*)(g_kl + di) = __halves2bfloat162(l0, l1);
                        }
                    }
                }
            }
        }
    }
}

// ============================================================================
// FLASH attention: per (bh, 64 q-rows), 128 threads, single K/V stage
// (Kh, Kl, Vh fp16), 4 CTAs/SM. Scores: 3-term bf16. PV: 1 fp16 mma.
// ============================================================================
__global__ __launch_bounds__(128, 4) void flash_kernel()
{
    extern __shared__ __align__(16) __nv_bfloat16 dynsm[];

    const int bh = blockIdx.y;
    const int m0 = blockIdx.x * 64;
    const int tid = threadIdx.x;
    const int wid = tid >> 5;          // 0..3
    const int lane = tid & 31;

    const __nv_bfloat16* Qh = g_qh + (size_t)bh * SS_ * HD;
    const __nv_bfloat16* Ql = g_ql + (size_t)bh * SS_ * HD;
    const __nv_bfloat16* Kh = g_kh + (size_t)bh * SS_ * HD;
    const __nv_bfloat16* Kl = g_kl + (size_t)bh * SS_ * HD;
    const __half* Vh = g_vth + (size_t)bh * HD * SS_;

    const uint32_t sbase = smem_u32(dynsm);
    const uint32_t sQh = sbase;
    const uint32_t sQl = sbase + (uint32_t)(64 * LDSB) * 2u;
    const uint32_t stb = sbase + F_Q_BYTES;      // single stage
    const uint32_t sKh = stb;
    const uint32_t sKl = stb + (uint32_t)(64 * LDSB) * 2u;
    const uint32_t sVh = stb + (uint32_t)(2 * 64 * LDSB) * 2u;

    const int a_r = lane & 15;
    const int a_c = (lane >> 4) << 3;
    const int b_r = ((lane >> 4) << 3) | (lane & 7);
    const int b_c = ((lane >> 3) & 1) << 3;
    const int er = lane >> 2;
    const int ec = (lane & 3) * 2;

    // ---- load Q tile ----
    for (int idx = tid; idx < 1024; idx += 128) {
        int c = idx & 7;
        int r = (idx >> 3) & 63;
        int sel = idx >> 9;
        const __nv_bfloat16* src = (sel ? Ql : Qh) + (size_t)(m0 + r) * HD;
        uint32_t dst = (sel ? sQl : sQh) + (uint32_t)(r * LDSB + c * 8) * 2u;
        uint4 val = ((const uint4*)src)[c];
        *(uint4*)(dynsm + (dst - sbase) / 2) = val;
    }

    auto fill = [&](int kt) {
        const int k0 = kt * 64;
        for (int idx = tid; idx < 1536; idx += 128) {
            int c = idx & 7;
            int r = (idx >> 3) & 63;
            int sel = idx >> 9;      // 0 Kh, 1 Kl, 2 Vh
            const void* src;
            if (sel == 0)      src = Kh + (size_t)(k0 + r) * HD + c * 8;
            else if (sel == 1) src = Kl + (size_t)(k0 + r) * HD + c * 8;
            else               src = Vh + (size_t)r * SS_ + k0 + c * 8;
            uint32_t daddr = stb + (uint32_t)(sel * 64 * LDSB + r * LDSB + c * 8) * 2u;
            cp_async16(daddr, src);
        }
    };

    __syncthreads();   // Q tile visible

    uint32_t qfh[4][4], qfl[4][4];
#pragma unroll
    for (int ks = 0; ks < 4; ks++) {
        uint32_t off = (uint32_t)((wid * 16 + a_r) * LDSB + ks * 16 + a_c) * 2u;
        ldsm4(qfh[ks], sQh + off);
        ldsm4(qfl[ks], sQl + off);
    }

    float o[8][4] = {};
    float mr0 = -1e30f, mr1 = -1e30f, lr0 = 0.f, lr1 = 0.f;

    for (int kt = 0; kt < 32; ++kt) {
        fill(kt);
        cp_async_commit();
        cp_async_wait0();
        __syncthreads();

        // ---- scores: 3-term bf16 ----
        float s[8][4] = {};
#pragma unroll
        for (int ks = 0; ks < 4; ks++) {
            uint32_t bfh[4][4], bfl[4][4];
#pragma unroll
            for (int jn = 0; jn < 4; jn++) {
                uint32_t off = (uint32_t)((jn * 16 + b_r) * LDSB + ks * 16 + b_c) * 2u;
                ldsm4(bfh[jn], sKh + off);
                ldsm4(bfl[jn], sKl + off);
            }
#pragma unroll
            for (int jn = 0; jn < 4; jn++)
#pragma unroll
                for (int hf = 0; hf < 2; hf++) {
                    int j8 = jn * 2 + hf;
                    mma16816(s[j8], qfh[ks], &bfh[jn][hf * 2]);
                    mma16816(s[j8], qfh[ks], &bfl[jn][hf * 2]);
                    mma16816(s[j8], qfl[ks], &bfh[jn][hf * 2]);
                }
        }

        // ---- online softmax ----
        float mx0 = -1e30f, mx1 = -1e30f;
#pragma unroll
        for (int j8 = 0; j8 < 8; j8++) {
            mx0 = fmaxf(mx0, fmaxf(s[j8][0], s[j8][1]));
            mx1 = fmaxf(mx1, fmaxf(s[j8][2], s[j8][3]));
        }
        mx0 = fmaxf(mx0, __shfl_xor_sync(~0u, mx0, 1));
        mx0 = fmaxf(mx0, __shfl_xor_sync(~0u, mx0, 2));
        mx1 = fmaxf(mx1, __shfl_xor_sync(~0u, mx1, 1));
        mx1 = fmaxf(mx1, __shfl_xor_sync(~0u, mx1, 2));

        float nm0 = fmaxf(mr0, mx0), nm1 = fmaxf(mr1, mx1);
        float c0 = __expf(mr0 - nm0), c1 = __expf(mr1 - nm1);

        float sum0 = 0.f, sum1 = 0.f;
#pragma unroll
        for (int j8 = 0; j8 < 8; j8++) {
            s[j8][0] = __expf(s[j8][0] - nm0); sum0 += s[j8][0];
            s[j8][1] = __expf(s[j8][1] - nm0); sum0 += s[j8][1];
            s[j8][2] = __expf(s[j8][2] - nm1); sum1 += s[j8][2];
            s[j8][3] = __expf(s[j8][3] - nm1); sum1 += s[j8][3];
        }
        sum0 += __shfl_xor_sync(~0u, sum0, 1);
        sum0 += __shfl_xor_sync(~0u, sum0, 2);
        sum1 += __shfl_xor_sync(~0u, sum1, 1);
        sum1 += __shfl_xor_sync(~0u, sum1, 2);

        lr0 = lr0 * c0 + sum0;
        lr1 = lr1 * c1 + sum1;
        mr0 = nm0; mr1 = nm1;

#pragma unroll
        for (int j8 = 0; j8 < 8; j8++) {
            o[j8][0] *= c0; o[j8][1] *= c0;
            o[j8][2] *= c1; o[j8][3] *= c1;
        }

        // ---- P -> fp16 fragments (also spill values) ----
        uint32_t pf[4][4];
#pragma unroll
        for (int u = 0; u < 4; u++) {
            const float* pa = s[2 * u];
            const float* pb = s[2 * u + 1];
            __half2 t;
            t = __floats2half2_rn(pa[0], pa[1]); pf[u][0] = *(uint32_t*)&t;
            t = __floats2half2_rn(pa[2], pa[3]); pf[u][1] = *(uint32_t*)&t;
            t = __floats2half2_rn(pb[0], pb[1]); pf[u][2] = *(uint32_t*)&t;
            t = __floats2half2_rn(pb[2], pb[3]); pf[u][3] = *(uint32_t*)&t;
        }

        // ---- spill P16 + tile max ----
        {
            const int q0 = m0 + wid * 16 + er;
            uint32_t* P0 = (uint32_t*)(g_p16 + (size_t)bh * SSQ + (size_t)q0 * SS_ + kt * 64 + ec);
            uint32_t* P1 = (uint32_t*)(g_p16 + (size_t)bh * SSQ + (size_t)(q0 + 8) * SS_ + kt * 64 + ec);
#pragma unroll
            for (int u = 0; u < 4; u++) {
                P0[(2 * u) * 4]     = pf[u][0];
                P0[(2 * u + 1) * 4] = pf[u][2];
                P1[(2 * u) * 4]     = pf[u][1];
                P1[(2 * u + 1) * 4] = pf[u][3];
            }
            if ((lane & 3) == 0) {
                size_t ti = ((size_t)bh * 32 + kt) * SS_ + q0;
                g_tm[ti] = nm0;
                g_tm[ti + 8] = nm1;
            }
        }

        // ---- PV: o += P16 @ Vh16  (1 fp16 mma) ----
#pragma unroll
        for (int u = 0; u < 4; u++) {
#pragma unroll
            for (int jn = 0; jn < 4; jn++) {
                uint32_t off = (uint32_t)((jn * 16 + b_r) * LDSB + u * 16 + b_c) * 2u;
                uint32_t vfh[4];
                ldsm4(vfh, sVh + off);
#pragma unroll
                for (int hf = 0; hf < 2; hf++) {
                    int j8 = jn * 2 + hf;
                    mma16816f(o[j8], pf[u], &vfh[hf * 2]);
                }
            }
        }
        __syncthreads();   // all warps done reading stage before next fill
    }

    // ---- epilogue: normalize, write ctx + stats ----
    const float inv0 = 1.0f / lr0, inv1 = 1.0f / lr1;
    const int b = bh >> 4, h = bh & 15;
#pragma unroll
    for (int j8 = 0; j8 < 8; j8++) {
#pragma unroll
        for (int half = 0; half < 2; half++) {
            int m = m0 + wid * 16 + er + half * 8;
            int n = j8 * 8 + ec;
            float inv = half ? inv1 : inv0;
            float v0 = o[j8][half * 2 + 0] * inv;
            float v1 = o[j8][half * 2 + 1] * inv;
            __nv_bfloat16 h0, l0, h1, l1;
            split2(v0, h0, l0);
            split2(v1, h1, l1);
            size_t di = ((size_t)(b * SS_ + m)) * DD + h * HD + n;
            *(__nv_bfloat162*)(g_ch + di) = __halves2bfloat162(h0, h1);
            *(__nv_bfloat162*)(g_cl + di) = __halves2bfloat162(l0, l1);
        }
    }
    if ((lane & 3) == 0) {
        size_t r0 = (size_t)bh * SS_ + m0 + wid * 16 + er;
        g_sm[r0] = mr0;      g_sl[r0] = lr0;
        g_sm[r0 + 8] = mr1;  g_sl[r0 + 8] = lr1;
    }
}

// ============================================================================
// mean kernel: pure streaming pass over P16 (validated R13).
// ============================================================================
__global__ __launch_bounds__(256) void mean_kernel(float* __restrict__ attn_mean)
{
    const int bq = blockIdx.x;           // 0..B*S-1
    const int b = bq >> 11;
    const int q = bq & (SS_ - 1);
    const int tid = threadIdx.x;
    const int col0 = tid * 8;
    const int kt = tid >> 3;

    float acc[8] = {};

    for (int h = 0; h < HH; h++) {
        const int bh = b * HH + h;
        const size_t srow = (size_t)bh * SS_ + q;
        float f = __expf(g_tm[((size_t)bh * 32 + kt) * SS_ + q] - g_sm[srow]) / g_sl[srow];

        uint4 pv = *(const uint4*)(g_p16 + (size_t)bh * SSQ + (size_t)q * SS_ + col0);
        const __half2* ph = (const __half2*)&pv;
#pragma unroll
        for (int j = 0; j < 4; j++) {
            float2 v = __half22float2(ph[j]);
            acc[2 * j]     += v.x * f;
            acc[2 * j + 1] += v.y * f;
        }
    }

    const float inv16 = 1.0f / 16.0f;
    float* dst = attn_mean + (size_t)bq * SS_ + col0;
    float4 o0 = make_float4(acc[0] * inv16, acc[1] * inv16, acc[2] * inv16, acc[3] * inv16);
    float4 o1 = make_float4(acc[4] * inv16, acc[5] * inv16, acc[6] * inv16, acc[7] * inv16);
    *(float4*)(dst) = o0;
    *(float4*)(dst + 4) = o1;
}

// ============================================================================
extern "C" void kernel_launch(void* const* d_in, const int* in_sizes, int n_in,
                              void* d_out, int out_size)
{
    const float* x  = (const float*)d_in[0];
    const float* Wq = (const float*)d_in[1];
    const float* bq = (const float*)d_in[2];
    const float* Wk = (const float*)d_in[3];
    const float* bk = (const float*)d_in[4];
    const float* Wv = (const float*)d_in[5];
    const float* bv = (const float*)d_in[6];
    const float* Wo = (const float*)d_in[7];
    const float* bo = (const float*)d_in[8];

    float* out = (float*)d_out;                        // [B,S,D]
    float* attn_mean = out + (size_t)BB * SS_ * DD;    // [B,S,S]

    cudaFuncSetAttribute(gemm_mma_kernel, cudaFuncAttributeMaxDynamicSharedMemorySize, G_PIPE_SMEM);
    cudaFuncSetAttribute(flash_kernel,    cudaFuncAttributeMaxDynamicSharedMemorySize, F_SMEM);

    // prep
    split_x_kernel<<<(M_TOT * DD + 255) / 256, 256>>>(x);
    dim3 tw(32, 8), gw(DD / 32, DD / 32, 4);
    transpose_split_w_kernel<<<gw, tw>>>(Wq, Wk, Wv, Wo);

    // q/k/v projections fused (mode = blockIdx.z)
    dim3 gqkv(M_TOT / 128, DD / 128, 3); // (32,8,3)
    gemm_mma_kernel<<<gqkv, 256, G_PIPE_SMEM>>>(-1, bq, bk, bv, nullptr);

    // flash attention: ctx + stats + P16 spill (4 CTAs/SM)
    dim3 gf(SS_ / 64, BH);               // (32,32)
    flash_kernel<<<gf, 128, F_SMEM>>>();

    // attn_mean: streaming pass
    mean_kernel<<<BB * SS_, 256>>>(attn_mean);

    // out projection
    dim3 gp(M_TOT / 128, DD / 128);      // (32,8)
    gemm_mma_kernel<<<gp, 256, G_PIPE_SMEM>>>(3, bo, nullptr, nullptr, out);
}